// round 14
// baseline (speedup 1.0000x reference)
#include <cuda_runtime.h>
#include <cuda_fp16.h>
#include <cstdint>

// out[b,i] = sum_h W2[i,h] * relu( sum_d X[b,d]*Adj[i,d]*W1[i,h,d] )
// B=16384, D=64, H=64.
//
// Single-term fp16 HMMA (mma.sync m16n8k16 f32.f16.f16).
// Block = (1 node x 512 rows) = 4 tiles of 128 rows (2048 blocks -> 6.9
// waves, tiny tail). 8 warps; warp = 16-row strip, all 64 h. B fragments
// register-resident (64 regs). X strips warp-private, cp.async with
// prefetch depth 2 (3 buffers, wait_group 1 steady-state). Epilogue on the
// tensor pipe: relu(H) packed to fp16 A fragments (pack + hmax2), W2 as a
// single-column B fragment -> 4 chained MMAs replace FMA+shfl chains.

#define NT   256
#define TB   128
#define TPB  4      // tiles per block

// ---- device-global fp16 buffers (prep output) ----
static __device__ __align__(16) __half Xf_g[16384 * 64];
static __device__ __align__(16) __half Wf_g[64 * 64 * 64];

// ---- main-kernel smem layout (bytes) ----
#define OFF_W    0        // 8KB, swizzled
#define OFF_X    8192     // 8 warps x 3 bufs x 2KB, swizzled
#define SMEM_TOTAL 57344

static __device__ __forceinline__ uint32_t h2u(__half2 h) {
    return *(uint32_t*)&h;
}

static __device__ __forceinline__ uint32_t smem_u32(const void* p) {
    uint32_t a;
    asm("{ .reg .u64 t; cvta.to.shared.u64 t, %1; cvt.u32.u64 %0, t; }" : "=r"(a) : "l"(p));
    return a;
}

static __device__ __forceinline__ void cp16(uint32_t dst, const void* src) {
    asm volatile("cp.async.ca.shared.global [%0], [%1], 16;"
                 :: "r"(dst), "l"(src) : "memory");
}

static __device__ __forceinline__ void ldsm4(uint32_t* r, uint32_t addr) {
    asm volatile("ldmatrix.sync.aligned.m8n8.x4.shared.b16 {%0,%1,%2,%3}, [%4];"
                 : "=r"(r[0]), "=r"(r[1]), "=r"(r[2]), "=r"(r[3]) : "r"(addr));
}

static __device__ __forceinline__ void mma16816(float* c, const uint32_t* a,
                                                const uint32_t* b) {
    asm volatile(
        "mma.sync.aligned.m16n8k16.row.col.f32.f16.f16.f32 "
        "{%0,%1,%2,%3}, {%4,%5,%6,%7}, {%8,%9}, {%0,%1,%2,%3};"
        : "+f"(c[0]), "+f"(c[1]), "+f"(c[2]), "+f"(c[3])
        : "r"(a[0]), "r"(a[1]), "r"(a[2]), "r"(a[3]), "r"(b[0]), "r"(b[1]));
}

// pack two f32 -> half2, relu in half2 (one HMNMX2 instead of two FMNMX)
static __device__ __forceinline__ uint32_t packrelu(float a, float b) {
    __half2 h = __floats2half2_rn(a, b);
    __half2 z = __float2half2_rn(0.f);
    return h2u(__hmax2(h, z));
}

// ---- prep: X -> fp16; W1*adj -> fp16 ----
__global__ __launch_bounds__(NT)
void prep_kernel(const float* __restrict__ X,
                 const float* __restrict__ Adj,
                 const float* __restrict__ W1)
{
    int gid = blockIdx.x * NT + threadIdx.x;
    if (gid < 262144) {                       // X: 16384*64/4 float4s
        float4 v = ((const float4*)X)[gid];
        uint2 r;
        r.x = h2u(__floats2half2_rn(v.x, v.y));
        r.y = h2u(__floats2half2_rn(v.z, v.w));
        ((uint2*)Xf_g)[gid] = r;
    } else {                                  // W: 64*64*64/4 float4s
        int j = gid - 262144;                 // 0..65535
        int i  = j >> 10;
        int d4 = j & 15;
        float4 v = ((const float4*)W1)[j];
        float4 a = ((const float4*)Adj)[i * 16 + d4];
        v.x *= a.x; v.y *= a.y; v.z *= a.z; v.w *= a.w;
        uint2 r;
        r.x = h2u(__floats2half2_rn(v.x, v.y));
        r.y = h2u(__floats2half2_rn(v.z, v.w));
        ((uint2*)Wf_g)[j] = r;
    }
}

// stage one 16-row strip of a tile into a warp buffer (4 cp16 per lane)
static __device__ __forceinline__ void stage_strip(uint32_t xdst,
                                                   const char* xsrc, int l) {
    #pragma unroll
    for (int it = 0; it < 4; ++it) {
        int c  = l + it * 32;               // 0..127
        int rl = c >> 3, k16 = c & 7;       // row-in-strip, 16B chunk
        cp16(xdst + rl * 128 + ((k16 ^ (rl & 7)) << 4),
             xsrc + (size_t)rl * 128 + k16 * 16);
    }
}

// ---- main GEMM ----
__global__ __launch_bounds__(NT, 2)
void tp_kernel(const float* __restrict__ W2, float* __restrict__ out)
{
    extern __shared__ char smem[];
    const uint32_t sb = smem_u32(smem);
    const int tid = threadIdx.x;
    const int wid = tid >> 5;
    const int l   = tid & 31;
    const int i    = blockIdx.x;                // node (fastest -> X L2 reuse)
    const int row0 = blockIdx.y * (TB * TPB);   // 512-row group

    const uint32_t xwarp = sb + OFF_X + wid * 6144;   // 3 x 2KB buffers
    const char* xbase = (const char*)(Xf_g + (size_t)(row0 + wid * 16) * 64);

    // ---- prologue group 0: W (8KB) + X tile 0 ----
    {
        const char* wsrc = (const char*)(Wf_g + (size_t)i * 4096);
        #pragma unroll
        for (int it = 0; it < 2; ++it) {
            int c = tid + it * NT;          // 0..511
            int r = c >> 3, k16 = c & 7;
            cp16(sb + OFF_W + r * 128 + ((k16 ^ (r & 7)) << 4), wsrc + c * 16);
        }
    }
    stage_strip(xwarp, xbase, l);
    asm volatile("cp.async.commit_group;" ::: "memory");
    // ---- prologue group 1: X tile 1 ----
    stage_strip(xwarp + 2048, xbase + (size_t)TB * 128, l);
    asm volatile("cp.async.commit_group;" ::: "memory");

    // ---- W2 epilogue B fragments: only n-col 0 populated (lanes l<4) ----
    uint32_t b2[4][2];
    {
        const float* w2p = W2 + i * 64;
        #pragma unroll
        for (int kc = 0; kc < 4; ++kc) {
            if (l < 4) {
                b2[kc][0] = h2u(__floats2half2_rn(w2p[kc * 16 + 2 * l],
                                                  w2p[kc * 16 + 2 * l + 1]));
                b2[kc][1] = h2u(__floats2half2_rn(w2p[kc * 16 + 8 + 2 * l],
                                                  w2p[kc * 16 + 8 + 2 * l + 1]));
            } else {
                b2[kc][0] = 0u;
                b2[kc][1] = 0u;
            }
        }
    }

    asm volatile("cp.async.wait_group 1;" ::: "memory");  // W + X0 done
    __syncthreads();   // W visibility (only block-wide sync)

    // ---- load ALL B fragments once (register-resident, 64 regs) ----
    const uint32_t bhalf = (l >> 3) & 1;
    uint32_t wv[4][4][4];                   // [ks][g][frag]
    #pragma unroll
    for (int g = 0; g < 4; ++g) {
        int brow = g * 16 + ((l >> 4) & 1) * 8 + (l & 7);
        uint32_t boff = sb + OFF_W + brow * 128;
        uint32_t bsw  = brow & 7;
        #pragma unroll
        for (int ks = 0; ks < 4; ++ks)
            ldsm4(wv[ks][g], boff + (((ks * 2 + bhalf) ^ bsw) << 4));
    }

    // A geometry: 16 rows in own strip
    const int arow = l & 15;
    const uint32_t asw  = arow & 7;
    const uint32_t ahalf = (l >> 4) & 1;

    #pragma unroll
    for (int t = 0; t < TPB; ++t) {
        if (t >= 1) {
            // tile t's fill complete (keep newest group pending until last)
            if (t < TPB - 1) {
                asm volatile("cp.async.wait_group 1;" ::: "memory");
            } else {
                asm volatile("cp.async.wait_group 0;" ::: "memory");
            }
            __syncwarp();
        }
        // prefetch tile t+2 (depth-2: two tiles of compute to land)
        if (t + 2 < TPB) {
            stage_strip(xwarp + ((t + 2) % 3) * 2048,
                        xbase + (size_t)(t + 2) * TB * 128, l);
            asm volatile("cp.async.commit_group;" ::: "memory");
        }

        const uint32_t aoff = xwarp + (uint32_t)((t % 3) * 2048) + arow * 128;

        float acc[8][4];
        #pragma unroll
        for (int n = 0; n < 8; ++n)
            #pragma unroll
            for (int q = 0; q < 4; ++q) acc[n][q] = 0.f;

        #pragma unroll
        for (int ks = 0; ks < 4; ++ks) {
            uint32_t xv[4];
            ldsm4(xv, aoff + (((ks * 2 + ahalf) ^ asw) << 4));
            #pragma unroll
            for (int n = 0; n < 8; ++n)
                mma16816(acc[n], xv, &wv[ks][n >> 1][(n & 1) * 2]);
        }

        // ---- epilogue on tensor pipe: out = relu(H) @ W2 ----
        float co[4] = {0.f, 0.f, 0.f, 0.f};
        #pragma unroll
        for (int kc = 0; kc < 4; ++kc) {
            uint32_t af[4];
            af[0] = packrelu(acc[2 * kc][0],     acc[2 * kc][1]);
            af[1] = packrelu(acc[2 * kc][2],     acc[2 * kc][3]);
            af[2] = packrelu(acc[2 * kc + 1][0], acc[2 * kc + 1][1]);
            af[3] = packrelu(acc[2 * kc + 1][2], acc[2 * kc + 1][3]);
            mma16816(co, af, b2[kc]);
        }
        // col 0 lives in lanes l%4==0: c0 = row l/4, c2 = row l/4+8
        if ((l & 3) == 0) {
            int grow = row0 + t * TB + wid * 16 + (l >> 2);
            out[(size_t)grow * 64 + i]       = co[0];
            out[(size_t)(grow + 8) * 64 + i] = co[2];
        }
    }
}

extern "C" void kernel_launch(void* const* d_in, const int* in_sizes, int n_in,
                              void* d_out, int out_size) {
    const float* X   = (const float*)d_in[0];  // [16384, 64]
    const float* Adj = (const float*)d_in[1];  // [64, 64]
    const float* W1  = (const float*)d_in[2];  // [64, 64, 64] (i,h,d)
    const float* W2  = (const float*)d_in[3];  // [64, 64]
    float* out = (float*)d_out;                // [16384, 64]

    prep_kernel<<<1280, NT>>>(X, Adj, W1);

    cudaFuncSetAttribute(tp_kernel, cudaFuncAttributeMaxDynamicSharedMemorySize,
                         SMEM_TOTAL);
    dim3 grid(64, 16384 / (TB * TPB));
    tp_kernel<<<grid, NT, SMEM_TOTAL>>>(W2, out);
}

// round 15
// speedup vs baseline: 1.0656x; 1.0656x over previous
#include <cuda_runtime.h>
#include <cuda_fp16.h>
#include <cstdint>

// out[b,i] = sum_h W2[i,h] * relu( sum_d X[b,d]*Adj[i,d]*W1[i,h,d] )
// B=16384, D=64, H=64.
//
// Single-term fp16 HMMA (mma.sync m16n8k16 f32.f16.f16).
// Block = (1 node x 1024 rows) = 8 tiles of 128 rows; 8 warps; warp =
// 16-row strip, all 64 h. B fragments loaded ONCE per warp with 16 direct
// LDG.128 from prep-emitted fragment-order Wfrag_g (no smem, no ldsm, NO
// block-wide barrier anywhere). X strips warp-private, double-buffered
// cp.async + ldsm. Epilogue on the tensor pipe (relu->pack->2 split MMA
// chains + FADD merge).

#define NT   256
#define TB   128
#define TPB  8      // tiles per block

// ---- device-global buffers (prep output) ----
static __device__ __align__(16) __half Xf_g[16384 * 64];      // linear fp16 X
static __device__ __align__(16) uint4  Wfrag_g[64 * 16 * 32]; // frag-order W'

static __device__ __forceinline__ uint32_t h2u(__half2 h) {
    return *(uint32_t*)&h;
}

static __device__ __forceinline__ uint32_t smem_u32(const void* p) {
    uint32_t a;
    asm("{ .reg .u64 t; cvta.to.shared.u64 t, %1; cvt.u32.u64 %0, t; }" : "=r"(a) : "l"(p));
    return a;
}

static __device__ __forceinline__ void cp16(uint32_t dst, const void* src) {
    asm volatile("cp.async.ca.shared.global [%0], [%1], 16;"
                 :: "r"(dst), "l"(src) : "memory");
}

static __device__ __forceinline__ void ldsm4(uint32_t* r, uint32_t addr) {
    asm volatile("ldmatrix.sync.aligned.m8n8.x4.shared.b16 {%0,%1,%2,%3}, [%4];"
                 : "=r"(r[0]), "=r"(r[1]), "=r"(r[2]), "=r"(r[3]) : "r"(addr));
}

static __device__ __forceinline__ void mma16816(float* c, const uint32_t* a,
                                                const uint32_t* b) {
    asm volatile(
        "mma.sync.aligned.m16n8k16.row.col.f32.f16.f16.f32 "
        "{%0,%1,%2,%3}, {%4,%5,%6,%7}, {%8,%9}, {%0,%1,%2,%3};"
        : "+f"(c[0]), "+f"(c[1]), "+f"(c[2]), "+f"(c[3])
        : "r"(a[0]), "r"(a[1]), "r"(a[2]), "r"(a[3]), "r"(b[0]), "r"(b[1]));
}

// pack two f32 -> half2 with relu (F2FP.PACK + one HMNMX2)
static __device__ __forceinline__ uint32_t packrelu(float a, float b) {
    __half2 h = __floats2half2_rn(a, b);
    __half2 z = __float2half2_rn(0.f);
    return h2u(__hmax2(h, z));
}

// ---- prep: X -> linear fp16; W1*adj -> fragment-order fp16 ----
__global__ __launch_bounds__(NT)
void prep_kernel(const float* __restrict__ X,
                 const float* __restrict__ Adj,
                 const float* __restrict__ W1)
{
    int gid = blockIdx.x * NT + threadIdx.x;
    if (gid < 262144) {                       // X: 16384*64/4 float4s
        float4 v = ((const float4*)X)[gid];
        uint2 r;
        r.x = h2u(__floats2half2_rn(v.x, v.y));
        r.y = h2u(__floats2half2_rn(v.z, v.w));
        ((uint2*)Xf_g)[gid] = r;
    } else if (gid < 262144 + 32768) {
        // W fragments: j = (node*16 + w)*32 + l ; flat word = ks*16 + n*2 + r
        int j    = gid - 262144;
        int l    = j & 31;
        int w    = (j >> 5) & 15;
        int node = j >> 9;
        int gi = l >> 2, ti = l & 3;
        uint32_t vv[4];
        #pragma unroll
        for (int q = 0; q < 4; ++q) {
            int idx = w * 4 + q;
            int ks = idx >> 4, ng = (idx >> 1) & 7, r = idx & 1;
            int h0 = ng * 8 + gi;
            int d0 = ks * 16 + ti * 2 + r * 8;
            const float* w1p = W1 + ((size_t)node * 64 + h0) * 64;
            const float* ap  = Adj + node * 64;
            vv[q] = h2u(__floats2half2_rn(w1p[d0] * ap[d0],
                                          w1p[d0 + 1] * ap[d0 + 1]));
        }
        uint4 o; o.x = vv[0]; o.y = vv[1]; o.z = vv[2]; o.w = vv[3];
        Wfrag_g[j] = o;
    }
}

// stage one 16-row strip of a tile into a warp buffer (4 cp16 per lane)
static __device__ __forceinline__ void stage_strip(uint32_t xdst,
                                                   const char* xsrc, int l) {
    #pragma unroll
    for (int it = 0; it < 4; ++it) {
        int c  = l + it * 32;               // 0..127
        int rl = c >> 3, k16 = c & 7;       // row-in-strip, 16B chunk
        cp16(xdst + rl * 128 + ((k16 ^ (rl & 7)) << 4),
             xsrc + (size_t)rl * 128 + k16 * 16);
    }
}

// ---- main GEMM ----
__global__ __launch_bounds__(NT, 2)
void tp_kernel(const float* __restrict__ W2, float* __restrict__ out)
{
    __shared__ __align__(16) char smem[8 * 2 * 2048];   // X strips only, 32KB
    const uint32_t sb = smem_u32(smem);
    const int tid = threadIdx.x;
    const int wid = tid >> 5;
    const int l   = tid & 31;
    const int i    = blockIdx.x;                // node (fastest -> X L2 reuse)
    const int row0 = blockIdx.y * (TB * TPB);   // 1024-row group

    const uint32_t xwarp = sb + wid * 4096;     // warp-private 2x2KB
    const char* xbase = (const char*)(Xf_g + (size_t)(row0 + wid * 16) * 64);

    // ---- X tile 0 (own strip) ----
    stage_strip(xwarp, xbase, l);
    asm volatile("cp.async.commit_group;" ::: "memory");

    // ---- B fragments: 16 direct LDG.128, register-resident (64 regs) ----
    uint32_t wv[64];
    {
        const uint4* wp = Wfrag_g + i * 512 + l;
        #pragma unroll
        for (int w = 0; w < 16; ++w) {
            uint4 t = __ldg(wp + w * 32);
            wv[w * 4 + 0] = t.x; wv[w * 4 + 1] = t.y;
            wv[w * 4 + 2] = t.z; wv[w * 4 + 3] = t.w;
        }
    }

    // ---- W2 epilogue B fragments: only n-col 0 populated (lanes l<4) ----
    uint32_t b2[4][2];
    {
        const float* w2p = W2 + i * 64;
        #pragma unroll
        for (int kc = 0; kc < 4; ++kc) {
            if (l < 4) {
                b2[kc][0] = h2u(__floats2half2_rn(w2p[kc * 16 + 2 * l],
                                                  w2p[kc * 16 + 2 * l + 1]));
                b2[kc][1] = h2u(__floats2half2_rn(w2p[kc * 16 + 8 + 2 * l],
                                                  w2p[kc * 16 + 8 + 2 * l + 1]));
            } else {
                b2[kc][0] = 0u;
                b2[kc][1] = 0u;
            }
        }
    }

    // A geometry: 16 rows in own strip
    const int arow = l & 15;
    const uint32_t asw   = arow & 7;
    const uint32_t ahalf = (l >> 4) & 1;

    #pragma unroll 2
    for (int t = 0; t < TPB; ++t) {
        // own fill of tile t complete; make visible warp-wide
        asm volatile("cp.async.wait_group 0;" ::: "memory");
        __syncwarp();

        // prefetch own strip of tile t+1 (overlaps this tile's MMAs)
        if (t + 1 < TPB) {
            stage_strip(xwarp + (((t + 1) & 1) ? 2048u : 0u),
                        xbase + (size_t)(t + 1) * TB * 128, l);
            asm volatile("cp.async.commit_group;" ::: "memory");
        }

        const uint32_t aoff = xwarp + (uint32_t)((t & 1) * 2048) + arow * 128;

        float acc[8][4];
        #pragma unroll
        for (int n = 0; n < 8; ++n)
            #pragma unroll
            for (int q = 0; q < 4; ++q) acc[n][q] = 0.f;

        #pragma unroll
        for (int ks = 0; ks < 4; ++ks) {
            uint32_t xv[4];
            ldsm4(xv, aoff + (((ks * 2 + ahalf) ^ asw) << 4));
            #pragma unroll
            for (int n = 0; n < 8; ++n)
                mma16816(acc[n], xv, &wv[ks * 16 + n * 2]);
        }

        // ---- epilogue on tensor pipe: out = relu(H) @ W2 ----
        // two independent accumulator chains, merged with FADD
        float co0[4] = {0.f, 0.f, 0.f, 0.f};
        float co1[4] = {0.f, 0.f, 0.f, 0.f};
        #pragma unroll
        for (int kc = 0; kc < 4; ++kc) {
            uint32_t af[4];
            af[0] = packrelu(acc[2 * kc][0],     acc[2 * kc][1]);
            af[1] = packrelu(acc[2 * kc][2],     acc[2 * kc][3]);
            af[2] = packrelu(acc[2 * kc + 1][0], acc[2 * kc + 1][1]);
            af[3] = packrelu(acc[2 * kc + 1][2], acc[2 * kc + 1][3]);
            mma16816((kc & 1) ? co1 : co0, af, b2[kc]);
        }
        // col 0 lives in lanes l%4==0: row l/4 and row l/4+8
        if ((l & 3) == 0) {
            int grow = row0 + t * TB + wid * 16 + (l >> 2);
            out[(size_t)grow * 64 + i]       = co0[0] + co1[0];
            out[(size_t)(grow + 8) * 64 + i] = co0[2] + co1[2];
        }
    }
}

extern "C" void kernel_launch(void* const* d_in, const int* in_sizes, int n_in,
                              void* d_out, int out_size) {
    const float* X   = (const float*)d_in[0];  // [16384, 64]
    const float* Adj = (const float*)d_in[1];  // [64, 64]
    const float* W1  = (const float*)d_in[2];  // [64, 64, 64] (i,h,d)
    const float* W2  = (const float*)d_in[3];  // [64, 64]
    float* out = (float*)d_out;                // [16384, 64]

    prep_kernel<<<1152, NT>>>(X, Adj, W1);

    dim3 grid(64, 16384 / (TB * TPB));
    tp_kernel<<<grid, NT>>>(W2, out);
}